// round 12
// baseline (speedup 1.0000x reference)
#include <cuda_runtime.h>
#include <cuda_fp16.h>
#include <cstdint>

// Problem shape (fixed): B=2, S=2048 -> ROWS=4096, n=m=4096
#define ROWS_T 4096
#define NDIM   4096
#define MDIM   4096
#define NCODE  (MDIM * (NDIM / 8))   // 2,097,152 codewords

// Scratch (allocation-free rule: __device__ globals)
__device__ __half g_Xh[(size_t)ROWS_T * NDIM];   // fp16 rotated input
__device__ __half g_W [(size_t)MDIM   * NDIM];   // fp16 dequantized weights
__device__ __half g_C [(size_t)ROWS_T * MDIM];   // fp16 GEMM output

// ===========================================================================
// helpers
// ===========================================================================
__device__ __forceinline__ uint32_t smem_u32(const void* p) {
    uint32_t a;
    asm("{ .reg .u64 t; cvta.to.shared.u64 t, %1; cvt.u32.u64 %0, t; }" : "=r"(a) : "l"(p));
    return a;
}
__device__ __forceinline__ void cp_async16(uint32_t dst, const void* src) {
    asm volatile("cp.async.cg.shared.global [%0], [%1], 16;\n" :: "r"(dst), "l"(src));
}
#define CP_COMMIT() asm volatile("cp.async.commit_group;\n")
#define CP_WAIT1()  asm volatile("cp.async.wait_group 1;\n" ::: "memory")

#define SWZ(b) ((b) ^ (((b) >> 3) & 0x70))

#define LDSM4(r0, r1, r2, r3, addr) \
    asm volatile("ldmatrix.sync.aligned.m8n8.x4.shared.b16 {%0,%1,%2,%3}, [%4];" \
        : "=r"(r0), "=r"(r1), "=r"(r2), "=r"(r3) : "r"(addr))

#define MMA16816(d, a, b0, b1) \
    asm volatile("mma.sync.aligned.m16n8k16.row.col.f32.f16.f16.f32 " \
        "{%0,%1,%2,%3}, {%4,%5,%6,%7}, {%8,%9}, {%0,%1,%2,%3};" \
        : "+f"((d)[0]), "+f"((d)[1]), "+f"((d)[2]), "+f"((d)[3]) \
        : "r"((a)[0]), "r"((a)[1]), "r"((a)[2]), "r"((a)[3]), "r"(b0), "r"(b1))

// ===========================================================================
// Kernel 1: W = fp16( grid[Qidxs].reshape(m, n) ), 2 codewords/thread
// ===========================================================================
__global__ void dequant_kernel(const float* __restrict__ grid,
                               const int*   __restrict__ qidxs,
                               __half*      __restrict__ W) {
    int i0 = (blockIdx.x * blockDim.x + threadIdx.x) * 2;
    #pragma unroll
    for (int u = 0; u < 2; u++) {
        int i = i0 + u;
        int idx = qidxs[i];
        const float4* g4 = reinterpret_cast<const float4*>(grid) + (size_t)idx * 2;
        float4 a = g4[0], b = g4[1];
        __half2 h0 = __floats2half2_rn(a.x, a.y);
        __half2 h1 = __floats2half2_rn(a.z, a.w);
        __half2 h2 = __floats2half2_rn(b.x, b.y);
        __half2 h3 = __floats2half2_rn(b.z, b.w);
        uint4 o;
        o.x = *reinterpret_cast<uint32_t*>(&h0);
        o.y = *reinterpret_cast<uint32_t*>(&h1);
        o.z = *reinterpret_cast<uint32_t*>(&h2);
        o.w = *reinterpret_cast<uint32_t*>(&h3);
        reinterpret_cast<uint4*>(W)[i] = o;
    }
}

// ===========================================================================
// FWHT radix-16 butterfly on 16 registers
// ===========================================================================
__device__ __forceinline__ void fwht16(float v[16]) {
    #pragma unroll
    for (int h = 1; h < 16; h <<= 1) {
        #pragma unroll
        for (int j = 0; j < 16; j += 2 * h) {
            #pragma unroll
            for (int k = 0; k < h; k++) {
                float a = v[j + k], b = v[j + k + h];
                v[j + k]     = a + b;
                v[j + k + h] = a - b;
            }
        }
    }
}

// Reversed-order FWHT core (bits 8-11, then 4-7, then 0-3):
//   entry : v[i] = x[t + 256*i]    (strided, coalesced global loads)
//   exit  : v[i] = y[16*t + i]     (contiguous, vectorizable global stores)
// Padding phys(e) = e + (e>>4); all passes conflict-free.
__device__ __forceinline__ void fwht4096_rev(float v[16], float* s, int t) {
    fwht16(v);                                     // bits 8-11
    const int b3 = t + (t >> 4);
    #pragma unroll
    for (int i = 0; i < 16; i++) s[b3 + 272 * i] = v[i];
    __syncthreads();
    const int b2 = (t & 15) + 272 * (t >> 4);
    #pragma unroll
    for (int i = 0; i < 16; i++) v[i] = s[b2 + 17 * i];
    fwht16(v);                                     // bits 4-7
    #pragma unroll
    for (int i = 0; i < 16; i++) s[b2 + 17 * i] = v[i];
    __syncthreads();
    #pragma unroll
    for (int i = 0; i < 16; i++) v[i] = s[17 * t + i];
    fwht16(v);                                     // bits 0-3
}

// ===========================================================================
// Kernel 2: Xh[row] = fp16( FWHT(input[row] * SU) / 64 )
// ===========================================================================
__global__ __launch_bounds__(256)
void fwht_su_kernel(const float* __restrict__ in,
                    const float* __restrict__ su,
                    __half*      __restrict__ out) {
    __shared__ float s[4096 + 256];
    const int t = threadIdx.x;
    const size_t row = blockIdx.x;
    float v[16];
    const float* ip  = in + row * NDIM + t;
    const float* sup = su + t;
    #pragma unroll
    for (int i = 0; i < 16; i++) v[i] = ip[256 * i] * sup[256 * i];
    fwht4096_rev(v, s, t);
    // contiguous fp16 stores: 16 halves = 2 x uint4
    uint4 o[2];
    #pragma unroll
    for (int j = 0; j < 2; j++) {
        __half2 h0 = __floats2half2_rn(v[8*j+0] * 0.015625f, v[8*j+1] * 0.015625f);
        __half2 h1 = __floats2half2_rn(v[8*j+2] * 0.015625f, v[8*j+3] * 0.015625f);
        __half2 h2 = __floats2half2_rn(v[8*j+4] * 0.015625f, v[8*j+5] * 0.015625f);
        __half2 h3 = __floats2half2_rn(v[8*j+6] * 0.015625f, v[8*j+7] * 0.015625f);
        o[j].x = *reinterpret_cast<uint32_t*>(&h0);
        o[j].y = *reinterpret_cast<uint32_t*>(&h1);
        o[j].z = *reinterpret_cast<uint32_t*>(&h2);
        o[j].w = *reinterpret_cast<uint32_t*>(&h3);
    }
    uint4* op = reinterpret_cast<uint4*>(out + row * NDIM + 16 * t);
    op[0] = o[0]; op[1] = o[1];
}

// ===========================================================================
// Kernel 4: out = FWHT(C_fp16) * SV / 64
// ===========================================================================
__global__ __launch_bounds__(256)
void fwht_sv_kernel(const __half* __restrict__ C,
                    float*        __restrict__ out,
                    const float*  __restrict__ sv) {
    __shared__ float s[4096 + 256];
    const int t = threadIdx.x;
    const size_t row = blockIdx.x;
    float v[16];
    const __half* cp = C + row * MDIM + t;
    #pragma unroll
    for (int i = 0; i < 16; i++) v[i] = __half2float(cp[256 * i]);
    fwht4096_rev(v, s, t);
    // contiguous fp32 stores with SV * 1/64
    const float4* sv4 = reinterpret_cast<const float4*>(sv) + 4 * t;
    float4* op = reinterpret_cast<float4*>(out + row * MDIM + 16 * t);
    #pragma unroll
    for (int i = 0; i < 4; i++) {
        float4 sc = sv4[i];
        op[i] = make_float4(v[4*i+0] * sc.x * 0.015625f,
                            v[4*i+1] * sc.y * 0.015625f,
                            v[4*i+2] * sc.z * 0.015625f,
                            v[4*i+3] * sc.w * 0.015625f);
    }
}

// ===========================================================================
// Kernel 3: fp16 mma.sync GEMM  C = A @ B^T (R8-proven schedule, fp16 out)
// CTA tile 128x128x64; 4 warps (2M x 2N), warp tile 64x64.
// 3-stage cp.async pipeline, cross-tile fragment pipelining, 1 sync/k-tile.
// ===========================================================================
#define NST      3
#define A_ST     (128 * 128)
#define B_ST     (128 * 128)
#define STG      (A_ST + B_ST)        // 32 KB
#define GEMM_SMEM (NST * STG + 1024)  // 97 KB -> 2 CTAs/SM

__device__ __forceinline__ void load_stage(uint32_t s0, int st, int kt, int tid,
                                           const __half* Ab, const __half* Bb) {
    uint32_t sA = s0 + st * STG;
    uint32_t sB = sA + A_ST;
    #pragma unroll
    for (int it = 0; it < 16; it++) {
        int c = tid + it * 128;                  // 0..2047
        if (c < 1024) {                          // A: 128 rows x 8 chunks(16B)
            int rr = c >> 3, cc = c & 7;
            cp_async16(sA + SWZ(rr * 128 + cc * 16),
                       Ab + (size_t)rr * NDIM + kt * 64 + cc * 8);
        } else {                                 // B
            int b = c - 1024;
            int rr = b >> 3, cc = b & 7;
            cp_async16(sB + SWZ(rr * 128 + cc * 16),
                       Bb + (size_t)rr * NDIM + kt * 64 + cc * 8);
        }
    }
    CP_COMMIT();
}

__global__ __launch_bounds__(128, 2)
void gemm_fp16(const __half* __restrict__ A,
               const __half* __restrict__ B,
               __half*       __restrict__ C) {
    extern __shared__ char smraw[];
    const uint32_t s0 = (smem_u32(smraw) + 1023u) & ~1023u;
    const int tid  = threadIdx.x;
    const int wid  = tid >> 5;
    const int lane = tid & 31;
    const int g    = lane >> 2;
    const int t4   = lane & 3;
    const int wm   = (wid & 1) * 64;
    const int wn   = (wid >> 1) * 64;

    const int a_row = (lane & 7) + ((lane & 8)  ? 8 : 0);
    const int a_kx  = (lane & 16) ? 16 : 0;
    const int b_row = (lane & 7) + ((lane & 16) ? 8 : 0);
    const int b_kx  = (lane & 8)  ? 16 : 0;

    const __half* Ab = A + (size_t)(blockIdx.y * 128) * NDIM;
    const __half* Bb = B + (size_t)(blockIdx.x * 128) * NDIM;

    float c[4][8][4];
    #pragma unroll
    for (int i = 0; i < 4; i++)
        #pragma unroll
        for (int j = 0; j < 8; j++)
            #pragma unroll
            for (int k = 0; k < 4; k++) c[i][j][k] = 0.f;

    uint32_t af[2][4][4], bf[2][8][2];

    #define LOAD_FRAGS(buf, base, kb) do {                                      \
        const uint32_t _sA = (base);                                            \
        const uint32_t _sB = _sA + A_ST;                                        \
        _Pragma("unroll")                                                       \
        for (int mi = 0; mi < 4; mi++) {                                        \
            int row = wm + mi * 16 + a_row;                                     \
            uint32_t ad = _sA + row * 128 + (((kb) + a_kx) ^ ((row & 7) << 4)); \
            LDSM4(af[buf][mi][0], af[buf][mi][1], af[buf][mi][2], af[buf][mi][3], ad); \
        }                                                                       \
        _Pragma("unroll")                                                       \
        for (int nb = 0; nb < 4; nb++) {                                        \
            int row = wn + nb * 16 + b_row;                                     \
            uint32_t bd = _sB + row * 128 + (((kb) + b_kx) ^ ((row & 7) << 4)); \
            LDSM4(bf[buf][2*nb][0], bf[buf][2*nb][1],                           \
                  bf[buf][2*nb+1][0], bf[buf][2*nb+1][1], bd);                  \
        }                                                                       \
    } while (0)

    load_stage(s0, 0, 0, tid, Ab, Bb);
    load_stage(s0, 1, 1, tid, Ab, Bb);
    CP_WAIT1();
    __syncthreads();
    LOAD_FRAGS(0, s0, 0);

    const int KT = NDIM / 64;   // 64 k-tiles
    for (int kt = 0; kt < KT; kt++) {
        const uint32_t stage_cur = s0 + (kt % NST) * STG;
        const uint32_t stage_nxt = s0 + ((kt + 1) % NST) * STG;
        #pragma unroll
        for (int ks = 0; ks < 4; ks++) {
            const int cur = ks & 1, nxt = cur ^ 1;
            if (ks == 3) {
                if (kt + 1 < KT) {
                    CP_WAIT1();
                    __syncthreads();
                    LOAD_FRAGS(nxt, stage_nxt, 0);
                }
            } else {
                LOAD_FRAGS(nxt, stage_cur, (ks + 1) * 32);
            }
            if (ks == 0) {
                if (kt + 2 < KT) load_stage(s0, (kt + 2) % NST, kt + 2, tid, Ab, Bb);
                else             CP_COMMIT();    // keep pending-group count exact
            }
            #pragma unroll
            for (int mi = 0; mi < 4; mi++)
                #pragma unroll
                for (int ni = 0; ni < 8; ni++)
                    MMA16816(c[mi][ni], af[cur][mi], bf[cur][ni][0], bf[cur][ni][1]);
        }
    }
    #undef LOAD_FRAGS

    // epilogue: fp16 C (halves GEMM write + fwht_sv read traffic)
    __half* Cb = C + (size_t)(blockIdx.y * 128 + wm) * MDIM + blockIdx.x * 128 + wn;
    #pragma unroll
    for (int mi = 0; mi < 4; mi++) {
        #pragma unroll
        for (int ni = 0; ni < 8; ni++) {
            const int col = ni * 8 + 2 * t4;
            __half2 h0 = __floats2half2_rn(c[mi][ni][0], c[mi][ni][1]);
            __half2 h1 = __floats2half2_rn(c[mi][ni][2], c[mi][ni][3]);
            *reinterpret_cast<__half2*>(Cb + (size_t)(mi * 16 + g    ) * MDIM + col) = h0;
            *reinterpret_cast<__half2*>(Cb + (size_t)(mi * 16 + g + 8) * MDIM + col) = h1;
        }
    }
}

// ===========================================================================
// Launch: input, SU, SV, grid, Qidxs (metadata order)
// ===========================================================================
extern "C" void kernel_launch(void* const* d_in, const int* in_sizes, int n_in,
                              void* d_out, int out_size) {
    const float* input = (const float*)d_in[0];
    const float* SU    = (const float*)d_in[1];
    const float* SV    = (const float*)d_in[2];
    const float* grid  = (const float*)d_in[3];
    const int*   qidxs = (const int*)  d_in[4];
    float* out = (float*)d_out;

    __half* Xh = nullptr;
    __half* W  = nullptr;
    __half* C  = nullptr;
    cudaGetSymbolAddress((void**)&Xh, g_Xh);
    cudaGetSymbolAddress((void**)&W,  g_W);
    cudaGetSymbolAddress((void**)&C,  g_C);

    cudaFuncSetAttribute(gemm_fp16, cudaFuncAttributeMaxDynamicSharedMemorySize, GEMM_SMEM);

    // 1. dequantize codebook -> W (fp16)
    dequant_kernel<<<NCODE / 512, 256>>>(grid, qidxs, W);

    // 2. Xh = fp16( FWHT(input * SU) / 64 )
    fwht_su_kernel<<<ROWS_T, 256>>>(input, SU, Xh);

    // 3. C = fp16( Xh @ W^T )  (fp16 mma.sync, fp32 accumulate)
    dim3 gdim(MDIM / 128, ROWS_T / 128);
    gemm_fp16<<<gdim, 128, GEMM_SMEM>>>(Xh, W, C);

    // 4. out = FWHT(C) * SV / 64
    fwht_sv_kernel<<<ROWS_T, 256>>>(C, out, SV);
}

// round 13
// speedup vs baseline: 1.0224x; 1.0224x over previous
#include <cuda_runtime.h>
#include <cuda_fp16.h>
#include <cstdint>

// Problem shape (fixed): B=2, S=2048 -> ROWS=4096, n=m=4096
#define ROWS_T 4096
#define NDIM   4096
#define MDIM   4096
#define NCODE  (MDIM * (NDIM / 8))   // 2,097,152 codewords

// Scratch (allocation-free rule: __device__ globals)
__device__ __half g_Xh[(size_t)ROWS_T * NDIM];   // fp16 rotated input
__device__ __half g_W [(size_t)MDIM   * NDIM];   // fp16 dequantized weights
__device__ __half g_C [(size_t)ROWS_T * MDIM];   // fp16 GEMM output

// ===========================================================================
// helpers
// ===========================================================================
__device__ __forceinline__ uint32_t smem_u32(const void* p) {
    uint32_t a;
    asm("{ .reg .u64 t; cvta.to.shared.u64 t, %1; cvt.u32.u64 %0, t; }" : "=r"(a) : "l"(p));
    return a;
}
__device__ __forceinline__ void cp_async16(uint32_t dst, const void* src) {
    asm volatile("cp.async.cg.shared.global [%0], [%1], 16;\n" :: "r"(dst), "l"(src));
}
#define CP_COMMIT() asm volatile("cp.async.commit_group;\n")
#define CP_WAIT1()  asm volatile("cp.async.wait_group 1;\n" ::: "memory")

#define SWZ(b) ((b) ^ (((b) >> 3) & 0x70))

#define LDSM4(r0, r1, r2, r3, addr) \
    asm volatile("ldmatrix.sync.aligned.m8n8.x4.shared.b16 {%0,%1,%2,%3}, [%4];" \
        : "=r"(r0), "=r"(r1), "=r"(r2), "=r"(r3) : "r"(addr))

#define MMA16816(d, a, b0, b1) \
    asm volatile("mma.sync.aligned.m16n8k16.row.col.f32.f16.f16.f32 " \
        "{%0,%1,%2,%3}, {%4,%5,%6,%7}, {%8,%9}, {%0,%1,%2,%3};" \
        : "+f"((d)[0]), "+f"((d)[1]), "+f"((d)[2]), "+f"((d)[3]) \
        : "r"((a)[0]), "r"((a)[1]), "r"((a)[2]), "r"((a)[3]), "r"(b0), "r"(b1))

// ===========================================================================
// Kernel 1: W = fp16( grid[Qidxs].reshape(m, n) ), 2 codewords/thread
// ===========================================================================
__global__ void dequant_kernel(const float* __restrict__ grid,
                               const int*   __restrict__ qidxs,
                               __half*      __restrict__ W) {
    int i0 = (blockIdx.x * blockDim.x + threadIdx.x) * 2;
    #pragma unroll
    for (int u = 0; u < 2; u++) {
        int i = i0 + u;
        int idx = qidxs[i];
        const float4* g4 = reinterpret_cast<const float4*>(grid) + (size_t)idx * 2;
        float4 a = g4[0], b = g4[1];
        __half2 h0 = __floats2half2_rn(a.x, a.y);
        __half2 h1 = __floats2half2_rn(a.z, a.w);
        __half2 h2 = __floats2half2_rn(b.x, b.y);
        __half2 h3 = __floats2half2_rn(b.z, b.w);
        uint4 o;
        o.x = *reinterpret_cast<uint32_t*>(&h0);
        o.y = *reinterpret_cast<uint32_t*>(&h1);
        o.z = *reinterpret_cast<uint32_t*>(&h2);
        o.w = *reinterpret_cast<uint32_t*>(&h3);
        reinterpret_cast<uint4*>(W)[i] = o;
    }
}

// ===========================================================================
// FWHT radix-16 butterfly on 16 registers
// ===========================================================================
__device__ __forceinline__ void fwht16(float v[16]) {
    #pragma unroll
    for (int h = 1; h < 16; h <<= 1) {
        #pragma unroll
        for (int j = 0; j < 16; j += 2 * h) {
            #pragma unroll
            for (int k = 0; k < h; k++) {
                float a = v[j + k], b = v[j + k + h];
                v[j + k]     = a + b;
                v[j + k + h] = a - b;
            }
        }
    }
}

// Forward FWHT core (R8-proven):
//   entry : v[i] = x[16*t + i]    (contiguous, vectorized global loads)
//   exit  : v[i] = y[t + 256*i]   (strided scalar stores, coalesced per warp)
// Padding phys(e) = e + (e>>4); all passes conflict-free.
__device__ __forceinline__ void fwht4096_fwd(float v[16], float* s, int t) {
    fwht16(v);                                   // bits 0-3
    #pragma unroll
    for (int i = 0; i < 16; i++) s[17 * t + i] = v[i];
    __syncthreads();
    const int b2 = 272 * (t >> 4) + (t & 15);
    #pragma unroll
    for (int i = 0; i < 16; i++) v[i] = s[b2 + 17 * i];
    fwht16(v);                                   // bits 4-7
    #pragma unroll
    for (int i = 0; i < 16; i++) s[b2 + 17 * i] = v[i];
    __syncthreads();
    const int b3 = t + (t >> 4);
    #pragma unroll
    for (int i = 0; i < 16; i++) v[i] = s[b3 + 272 * i];
    fwht16(v);                                   // bits 8-11
}

// ===========================================================================
// Kernel 2: Xh[row] = fp16( FWHT(input[row] * SU) / 64 )   (R8-proven)
// ===========================================================================
__global__ __launch_bounds__(256)
void fwht_su_kernel(const float* __restrict__ in,
                    const float* __restrict__ su,
                    __half*      __restrict__ out) {
    __shared__ float s[4096 + 256];
    const int t = threadIdx.x;
    const size_t row = blockIdx.x;
    float v[16];
    const float4* in4 = reinterpret_cast<const float4*>(in + row * NDIM) + t * 4;
    const float4* su4 = reinterpret_cast<const float4*>(su) + t * 4;
    #pragma unroll
    for (int i = 0; i < 4; i++) {
        float4 a = in4[i], b = su4[i];
        v[4*i+0] = a.x * b.x; v[4*i+1] = a.y * b.y;
        v[4*i+2] = a.z * b.z; v[4*i+3] = a.w * b.w;
    }
    fwht4096_fwd(v, s, t);
    __half* o = out + row * NDIM + t;
    #pragma unroll
    for (int i = 0; i < 16; i++) o[256 * i] = __float2half_rn(v[i] * 0.015625f);
}

// ===========================================================================
// Kernel 4: out = FWHT(C_fp16) * SV / 64
// Contiguous fp16 loads (2 x LDG.128), strided coalesced fp32 stores.
// ===========================================================================
__global__ __launch_bounds__(256)
void fwht_sv_kernel(const __half* __restrict__ C,
                    float*        __restrict__ out,
                    const float*  __restrict__ sv) {
    __shared__ float s[4096 + 256];
    const int t = threadIdx.x;
    const size_t row = blockIdx.x;
    float v[16];
    const uint4* cp = reinterpret_cast<const uint4*>(C + row * MDIM + 16 * t);
    #pragma unroll
    for (int j = 0; j < 2; j++) {
        uint4 a = cp[j];
        const __half2* ah = reinterpret_cast<const __half2*>(&a);
        #pragma unroll
        for (int k = 0; k < 4; k++) {
            float2 f = __half22float2(ah[k]);
            v[8*j + 2*k + 0] = f.x;
            v[8*j + 2*k + 1] = f.y;
        }
    }
    fwht4096_fwd(v, s, t);
    float* o = out + row * MDIM + t;
    const float* svp = sv + t;
    #pragma unroll
    for (int i = 0; i < 16; i++) o[256 * i] = v[i] * svp[256 * i] * 0.015625f;
}

// ===========================================================================
// Kernel 3: fp16 mma.sync GEMM  C = A @ B^T (R8-proven schedule, fp16 out)
// CTA tile 128x128x64; 4 warps (2M x 2N), warp tile 64x64.
// 3-stage cp.async pipeline, cross-tile fragment pipelining, 1 sync/k-tile.
// ===========================================================================
#define NST      3
#define A_ST     (128 * 128)
#define B_ST     (128 * 128)
#define STG      (A_ST + B_ST)        // 32 KB
#define GEMM_SMEM (NST * STG + 1024)  // 97 KB -> 2 CTAs/SM

__device__ __forceinline__ void load_stage(uint32_t s0, int st, int kt, int tid,
                                           const __half* Ab, const __half* Bb) {
    uint32_t sA = s0 + st * STG;
    uint32_t sB = sA + A_ST;
    #pragma unroll
    for (int it = 0; it < 16; it++) {
        int c = tid + it * 128;                  // 0..2047
        if (c < 1024) {                          // A: 128 rows x 8 chunks(16B)
            int rr = c >> 3, cc = c & 7;
            cp_async16(sA + SWZ(rr * 128 + cc * 16),
                       Ab + (size_t)rr * NDIM + kt * 64 + cc * 8);
        } else {                                 // B
            int b = c - 1024;
            int rr = b >> 3, cc = b & 7;
            cp_async16(sB + SWZ(rr * 128 + cc * 16),
                       Bb + (size_t)rr * NDIM + kt * 64 + cc * 8);
        }
    }
    CP_COMMIT();
}

__global__ __launch_bounds__(128, 2)
void gemm_fp16(const __half* __restrict__ A,
               const __half* __restrict__ B,
               __half*       __restrict__ C) {
    extern __shared__ char smraw[];
    const uint32_t s0 = (smem_u32(smraw) + 1023u) & ~1023u;
    const int tid  = threadIdx.x;
    const int wid  = tid >> 5;
    const int lane = tid & 31;
    const int g    = lane >> 2;
    const int t4   = lane & 3;
    const int wm   = (wid & 1) * 64;
    const int wn   = (wid >> 1) * 64;

    const int a_row = (lane & 7) + ((lane & 8)  ? 8 : 0);
    const int a_kx  = (lane & 16) ? 16 : 0;
    const int b_row = (lane & 7) + ((lane & 16) ? 8 : 0);
    const int b_kx  = (lane & 8)  ? 16 : 0;

    const __half* Ab = A + (size_t)(blockIdx.y * 128) * NDIM;
    const __half* Bb = B + (size_t)(blockIdx.x * 128) * NDIM;

    float c[4][8][4];
    #pragma unroll
    for (int i = 0; i < 4; i++)
        #pragma unroll
        for (int j = 0; j < 8; j++)
            #pragma unroll
            for (int k = 0; k < 4; k++) c[i][j][k] = 0.f;

    uint32_t af[2][4][4], bf[2][8][2];

    #define LOAD_FRAGS(buf, base, kb) do {                                      \
        const uint32_t _sA = (base);                                            \
        const uint32_t _sB = _sA + A_ST;                                        \
        _Pragma("unroll")                                                       \
        for (int mi = 0; mi < 4; mi++) {                                        \
            int row = wm + mi * 16 + a_row;                                     \
            uint32_t ad = _sA + row * 128 + (((kb) + a_kx) ^ ((row & 7) << 4)); \
            LDSM4(af[buf][mi][0], af[buf][mi][1], af[buf][mi][2], af[buf][mi][3], ad); \
        }                                                                       \
        _Pragma("unroll")                                                       \
        for (int nb = 0; nb < 4; nb++) {                                        \
            int row = wn + nb * 16 + b_row;                                     \
            uint32_t bd = _sB + row * 128 + (((kb) + b_kx) ^ ((row & 7) << 4)); \
            LDSM4(bf[buf][2*nb][0], bf[buf][2*nb][1],                           \
                  bf[buf][2*nb+1][0], bf[buf][2*nb+1][1], bd);                  \
        }                                                                       \
    } while (0)

    load_stage(s0, 0, 0, tid, Ab, Bb);
    load_stage(s0, 1, 1, tid, Ab, Bb);
    CP_WAIT1();
    __syncthreads();
    LOAD_FRAGS(0, s0, 0);

    const int KT = NDIM / 64;   // 64 k-tiles
    for (int kt = 0; kt < KT; kt++) {
        const uint32_t stage_cur = s0 + (kt % NST) * STG;
        const uint32_t stage_nxt = s0 + ((kt + 1) % NST) * STG;
        #pragma unroll
        for (int ks = 0; ks < 4; ks++) {
            const int cur = ks & 1, nxt = cur ^ 1;
            if (ks == 3) {
                if (kt + 1 < KT) {
                    CP_WAIT1();
                    __syncthreads();
                    LOAD_FRAGS(nxt, stage_nxt, 0);
                }
            } else {
                LOAD_FRAGS(nxt, stage_cur, (ks + 1) * 32);
            }
            if (ks == 0) {
                if (kt + 2 < KT) load_stage(s0, (kt + 2) % NST, kt + 2, tid, Ab, Bb);
                else             CP_COMMIT();    // keep pending-group count exact
            }
            #pragma unroll
            for (int mi = 0; mi < 4; mi++)
                #pragma unroll
                for (int ni = 0; ni < 8; ni++)
                    MMA16816(c[mi][ni], af[cur][mi], bf[cur][ni][0], bf[cur][ni][1]);
        }
    }
    #undef LOAD_FRAGS

    // epilogue: fp16 C (halves GEMM write + fwht_sv read traffic)
    __half* Cb = C + (size_t)(blockIdx.y * 128 + wm) * MDIM + blockIdx.x * 128 + wn;
    #pragma unroll
    for (int mi = 0; mi < 4; mi++) {
        #pragma unroll
        for (int ni = 0; ni < 8; ni++) {
            const int col = ni * 8 + 2 * t4;
            __half2 h0 = __floats2half2_rn(c[mi][ni][0], c[mi][ni][1]);
            __half2 h1 = __floats2half2_rn(c[mi][ni][2], c[mi][ni][3]);
            *reinterpret_cast<__half2*>(Cb + (size_t)(mi * 16 + g    ) * MDIM + col) = h0;
            *reinterpret_cast<__half2*>(Cb + (size_t)(mi * 16 + g + 8) * MDIM + col) = h1;
        }
    }
}

// ===========================================================================
// Launch: input, SU, SV, grid, Qidxs (metadata order)
// ===========================================================================
extern "C" void kernel_launch(void* const* d_in, const int* in_sizes, int n_in,
                              void* d_out, int out_size) {
    const float* input = (const float*)d_in[0];
    const float* SU    = (const float*)d_in[1];
    const float* SV    = (const float*)d_in[2];
    const float* grid  = (const float*)d_in[3];
    const int*   qidxs = (const int*)  d_in[4];
    float* out = (float*)d_out;

    __half* Xh = nullptr;
    __half* W  = nullptr;
    __half* C  = nullptr;
    cudaGetSymbolAddress((void**)&Xh, g_Xh);
    cudaGetSymbolAddress((void**)&W,  g_W);
    cudaGetSymbolAddress((void**)&C,  g_C);

    cudaFuncSetAttribute(gemm_fp16, cudaFuncAttributeMaxDynamicSharedMemorySize, GEMM_SMEM);

    // 1. dequantize codebook -> W (fp16)
    dequant_kernel<<<NCODE / 512, 256>>>(grid, qidxs, W);

    // 2. Xh = fp16( FWHT(input * SU) / 64 )
    fwht_su_kernel<<<ROWS_T, 256>>>(input, SU, Xh);

    // 3. C = fp16( Xh @ W^T )  (fp16 mma.sync, fp32 accumulate)
    dim3 gdim(MDIM / 128, ROWS_T / 128);
    gemm_fp16<<<gdim, 128, GEMM_SMEM>>>(Xh, W, C);

    // 4. out = FWHT(C) * SV / 64
    fwht_sv_kernel<<<ROWS_T, 256>>>(C, out, SV);
}

// round 14
// speedup vs baseline: 1.0238x; 1.0014x over previous
#include <cuda_runtime.h>
#include <cuda_fp16.h>
#include <cstdint>

// Problem shape (fixed): B=2, S=2048 -> ROWS=4096, n=m=4096
#define ROWS_T 4096
#define NDIM   4096
#define MDIM   4096
#define NCODE  (MDIM * (NDIM / 8))   // 2,097,152 codewords
#define NB_DQ  (NCODE / 512)         // 4096 dequant blocks (2 codewords/thread)

// Scratch (allocation-free rule: __device__ globals)
__device__ __half g_Xh[(size_t)ROWS_T * NDIM];   // fp16 rotated input
__device__ __half g_W [(size_t)MDIM   * NDIM];   // fp16 dequantized weights
__device__ __half g_C [(size_t)ROWS_T * MDIM];   // fp16 GEMM output

// ===========================================================================
// helpers
// ===========================================================================
__device__ __forceinline__ uint32_t smem_u32(const void* p) {
    uint32_t a;
    asm("{ .reg .u64 t; cvta.to.shared.u64 t, %1; cvt.u32.u64 %0, t; }" : "=r"(a) : "l"(p));
    return a;
}
__device__ __forceinline__ void cp_async16(uint32_t dst, const void* src) {
    asm volatile("cp.async.cg.shared.global [%0], [%1], 16;\n" :: "r"(dst), "l"(src));
}
#define CP_COMMIT() asm volatile("cp.async.commit_group;\n")
#define CP_WAIT1()  asm volatile("cp.async.wait_group 1;\n" ::: "memory")

#define SWZ(b) ((b) ^ (((b) >> 3) & 0x70))

#define LDSM4(r0, r1, r2, r3, addr) \
    asm volatile("ldmatrix.sync.aligned.m8n8.x4.shared.b16 {%0,%1,%2,%3}, [%4];" \
        : "=r"(r0), "=r"(r1), "=r"(r2), "=r"(r3) : "r"(addr))

#define MMA16816(d, a, b0, b1) \
    asm volatile("mma.sync.aligned.m16n8k16.row.col.f32.f16.f16.f32 " \
        "{%0,%1,%2,%3}, {%4,%5,%6,%7}, {%8,%9}, {%0,%1,%2,%3};" \
        : "+f"((d)[0]), "+f"((d)[1]), "+f"((d)[2]), "+f"((d)[3]) \
        : "r"((a)[0]), "r"((a)[1]), "r"((a)[2]), "r"((a)[3]), "r"(b0), "r"(b1))

// ===========================================================================
// FWHT radix-16 butterfly on 16 registers
// ===========================================================================
__device__ __forceinline__ void fwht16(float v[16]) {
    #pragma unroll
    for (int h = 1; h < 16; h <<= 1) {
        #pragma unroll
        for (int j = 0; j < 16; j += 2 * h) {
            #pragma unroll
            for (int k = 0; k < h; k++) {
                float a = v[j + k], b = v[j + k + h];
                v[j + k]     = a + b;
                v[j + k + h] = a - b;
            }
        }
    }
}

// Forward FWHT core (R8-proven):
//   entry : v[i] = x[16*t + i]    (contiguous, vectorized global loads)
//   exit  : v[i] = y[t + 256*i]   (strided scalar stores, coalesced per warp)
// Padding phys(e) = e + (e>>4); all passes conflict-free.
__device__ __forceinline__ void fwht4096_fwd(float v[16], float* s, int t) {
    fwht16(v);                                   // bits 0-3
    #pragma unroll
    for (int i = 0; i < 16; i++) s[17 * t + i] = v[i];
    __syncthreads();
    const int b2 = 272 * (t >> 4) + (t & 15);
    #pragma unroll
    for (int i = 0; i < 16; i++) v[i] = s[b2 + 17 * i];
    fwht16(v);                                   // bits 4-7
    #pragma unroll
    for (int i = 0; i < 16; i++) s[b2 + 17 * i] = v[i];
    __syncthreads();
    const int b3 = t + (t >> 4);
    #pragma unroll
    for (int i = 0; i < 16; i++) v[i] = s[b3 + 272 * i];
    fwht16(v);                                   // bits 8-11
}

// ===========================================================================
// Kernel 1 (fused prep): blocks [0, NB_DQ)      -> dequant (2 codewords/thread)
//                        blocks [NB_DQ, +4096)  -> fwht_su rows
// __launch_bounds__(256, 8) caps regs at 32 -> full 8-block occupancy for both
// branches (R9's fusion failed at 39 regs / 6 blocks). Dequant blocks first so
// the latency-bound gathers start while fwht blocks stream.
// ===========================================================================
__global__ __launch_bounds__(256, 8)
void prep_kernel(const float* __restrict__ in,
                 const float* __restrict__ su,
                 const float* __restrict__ grid,
                 const int*   __restrict__ qidxs,
                 __half*      __restrict__ Xh,
                 __half*      __restrict__ W) {
    __shared__ float s[4096 + 256];
    const int t = threadIdx.x;

    if (blockIdx.x < NB_DQ) {
        // ---- dequant ----
        int i0 = (blockIdx.x * 256 + t) * 2;
        #pragma unroll
        for (int u = 0; u < 2; u++) {
            int i = i0 + u;
            int idx = qidxs[i];
            const float4* g4 = reinterpret_cast<const float4*>(grid) + (size_t)idx * 2;
            float4 a = g4[0], b = g4[1];
            __half2 h0 = __floats2half2_rn(a.x, a.y);
            __half2 h1 = __floats2half2_rn(a.z, a.w);
            __half2 h2 = __floats2half2_rn(b.x, b.y);
            __half2 h3 = __floats2half2_rn(b.z, b.w);
            uint4 o;
            o.x = *reinterpret_cast<uint32_t*>(&h0);
            o.y = *reinterpret_cast<uint32_t*>(&h1);
            o.z = *reinterpret_cast<uint32_t*>(&h2);
            o.w = *reinterpret_cast<uint32_t*>(&h3);
            reinterpret_cast<uint4*>(W)[i] = o;
        }
        return;
    }

    // ---- fwht_su ----
    const size_t row = blockIdx.x - NB_DQ;
    float v[16];
    const float4* in4 = reinterpret_cast<const float4*>(in + row * NDIM) + t * 4;
    const float4* su4 = reinterpret_cast<const float4*>(su) + t * 4;
    #pragma unroll
    for (int i = 0; i < 4; i++) {
        float4 a = in4[i], b = su4[i];
        v[4*i+0] = a.x * b.x; v[4*i+1] = a.y * b.y;
        v[4*i+2] = a.z * b.z; v[4*i+3] = a.w * b.w;
    }
    fwht4096_fwd(v, s, t);
    __half* o = Xh + row * NDIM + t;
    #pragma unroll
    for (int i = 0; i < 16; i++) o[256 * i] = __float2half_rn(v[i] * 0.015625f);
}

// ===========================================================================
// Kernel 4: out = FWHT(C_fp16) * SV / 64   (R13-proven)
// ===========================================================================
__global__ __launch_bounds__(256)
void fwht_sv_kernel(const __half* __restrict__ C,
                    float*        __restrict__ out,
                    const float*  __restrict__ sv) {
    __shared__ float s[4096 + 256];
    const int t = threadIdx.x;
    const size_t row = blockIdx.x;
    float v[16];
    const uint4* cp = reinterpret_cast<const uint4*>(C + row * MDIM + 16 * t);
    #pragma unroll
    for (int j = 0; j < 2; j++) {
        uint4 a = cp[j];
        const __half2* ah = reinterpret_cast<const __half2*>(&a);
        #pragma unroll
        for (int k = 0; k < 4; k++) {
            float2 f = __half22float2(ah[k]);
            v[8*j + 2*k + 0] = f.x;
            v[8*j + 2*k + 1] = f.y;
        }
    }
    fwht4096_fwd(v, s, t);
    float* o = out + row * MDIM + t;
    const float* svp = sv + t;
    #pragma unroll
    for (int i = 0; i < 16; i++) o[256 * i] = v[i] * svp[256 * i] * 0.015625f;
}

// ===========================================================================
// Kernel 3: fp16 mma.sync GEMM  C = A @ B^T (R8-proven schedule, fp16 out)
// CTA tile 128x128x64; 4 warps (2M x 2N), warp tile 64x64.
// 3-stage cp.async pipeline, cross-tile fragment pipelining, 1 sync/k-tile.
// ===========================================================================
#define NST      3
#define A_ST     (128 * 128)
#define B_ST     (128 * 128)
#define STG      (A_ST + B_ST)        // 32 KB
#define GEMM_SMEM (NST * STG + 1024)  // 97 KB -> 2 CTAs/SM

__device__ __forceinline__ void load_stage(uint32_t s0, int st, int kt, int tid,
                                           const __half* Ab, const __half* Bb) {
    uint32_t sA = s0 + st * STG;
    uint32_t sB = sA + A_ST;
    #pragma unroll
    for (int it = 0; it < 16; it++) {
        int c = tid + it * 128;                  // 0..2047
        if (c < 1024) {                          // A: 128 rows x 8 chunks(16B)
            int rr = c >> 3, cc = c & 7;
            cp_async16(sA + SWZ(rr * 128 + cc * 16),
                       Ab + (size_t)rr * NDIM + kt * 64 + cc * 8);
        } else {                                 // B
            int b = c - 1024;
            int rr = b >> 3, cc = b & 7;
            cp_async16(sB + SWZ(rr * 128 + cc * 16),
                       Bb + (size_t)rr * NDIM + kt * 64 + cc * 8);
        }
    }
    CP_COMMIT();
}

__global__ __launch_bounds__(128, 2)
void gemm_fp16(const __half* __restrict__ A,
               const __half* __restrict__ B,
               __half*       __restrict__ C) {
    extern __shared__ char smraw[];
    const uint32_t s0 = (smem_u32(smraw) + 1023u) & ~1023u;
    const int tid  = threadIdx.x;
    const int wid  = tid >> 5;
    const int lane = tid & 31;
    const int g    = lane >> 2;
    const int t4   = lane & 3;
    const int wm   = (wid & 1) * 64;
    const int wn   = (wid >> 1) * 64;

    const int a_row = (lane & 7) + ((lane & 8)  ? 8 : 0);
    const int a_kx  = (lane & 16) ? 16 : 0;
    const int b_row = (lane & 7) + ((lane & 16) ? 8 : 0);
    const int b_kx  = (lane & 8)  ? 16 : 0;

    const __half* Ab = A + (size_t)(blockIdx.y * 128) * NDIM;
    const __half* Bb = B + (size_t)(blockIdx.x * 128) * NDIM;

    float c[4][8][4];
    #pragma unroll
    for (int i = 0; i < 4; i++)
        #pragma unroll
        for (int j = 0; j < 8; j++)
            #pragma unroll
            for (int k = 0; k < 4; k++) c[i][j][k] = 0.f;

    uint32_t af[2][4][4], bf[2][8][2];

    #define LOAD_FRAGS(buf, base, kb) do {                                      \
        const uint32_t _sA = (base);                                            \
        const uint32_t _sB = _sA + A_ST;                                        \
        _Pragma("unroll")                                                       \
        for (int mi = 0; mi < 4; mi++) {                                        \
            int row = wm + mi * 16 + a_row;                                     \
            uint32_t ad = _sA + row * 128 + (((kb) + a_kx) ^ ((row & 7) << 4)); \
            LDSM4(af[buf][mi][0], af[buf][mi][1], af[buf][mi][2], af[buf][mi][3], ad); \
        }                                                                       \
        _Pragma("unroll")                                                       \
        for (int nb = 0; nb < 4; nb++) {                                        \
            int row = wn + nb * 16 + b_row;                                     \
            uint32_t bd = _sB + row * 128 + (((kb) + b_kx) ^ ((row & 7) << 4)); \
            LDSM4(bf[buf][2*nb][0], bf[buf][2*nb][1],                           \
                  bf[buf][2*nb+1][0], bf[buf][2*nb+1][1], bd);                  \
        }                                                                       \
    } while (0)

    load_stage(s0, 0, 0, tid, Ab, Bb);
    load_stage(s0, 1, 1, tid, Ab, Bb);
    CP_WAIT1();
    __syncthreads();
    LOAD_FRAGS(0, s0, 0);

    const int KT = NDIM / 64;   // 64 k-tiles
    for (int kt = 0; kt < KT; kt++) {
        const uint32_t stage_cur = s0 + (kt % NST) * STG;
        const uint32_t stage_nxt = s0 + ((kt + 1) % NST) * STG;
        #pragma unroll
        for (int ks = 0; ks < 4; ks++) {
            const int cur = ks & 1, nxt = cur ^ 1;
            if (ks == 3) {
                if (kt + 1 < KT) {
                    CP_WAIT1();
                    __syncthreads();
                    LOAD_FRAGS(nxt, stage_nxt, 0);
                }
            } else {
                LOAD_FRAGS(nxt, stage_cur, (ks + 1) * 32);
            }
            if (ks == 0) {
                if (kt + 2 < KT) load_stage(s0, (kt + 2) % NST, kt + 2, tid, Ab, Bb);
                else             CP_COMMIT();    // keep pending-group count exact
            }
            #pragma unroll
            for (int mi = 0; mi < 4; mi++)
                #pragma unroll
                for (int ni = 0; ni < 8; ni++)
                    MMA16816(c[mi][ni], af[cur][mi], bf[cur][ni][0], bf[cur][ni][1]);
        }
    }
    #undef LOAD_FRAGS

    // epilogue: fp16 C (halves GEMM write + fwht_sv read traffic)
    __half* Cb = C + (size_t)(blockIdx.y * 128 + wm) * MDIM + blockIdx.x * 128 + wn;
    #pragma unroll
    for (int mi = 0; mi < 4; mi++) {
        #pragma unroll
        for (int ni = 0; ni < 8; ni++) {
            const int col = ni * 8 + 2 * t4;
            __half2 h0 = __floats2half2_rn(c[mi][ni][0], c[mi][ni][1]);
            __half2 h1 = __floats2half2_rn(c[mi][ni][2], c[mi][ni][3]);
            *reinterpret_cast<__half2*>(Cb + (size_t)(mi * 16 + g    ) * MDIM + col) = h0;
            *reinterpret_cast<__half2*>(Cb + (size_t)(mi * 16 + g + 8) * MDIM + col) = h1;
        }
    }
}

// ===========================================================================
// Launch: input, SU, SV, grid, Qidxs (metadata order)
// ===========================================================================
extern "C" void kernel_launch(void* const* d_in, const int* in_sizes, int n_in,
                              void* d_out, int out_size) {
    const float* input = (const float*)d_in[0];
    const float* SU    = (const float*)d_in[1];
    const float* SV    = (const float*)d_in[2];
    const float* grid  = (const float*)d_in[3];
    const int*   qidxs = (const int*)  d_in[4];
    float* out = (float*)d_out;

    __half* Xh = nullptr;
    __half* W  = nullptr;
    __half* C  = nullptr;
    cudaGetSymbolAddress((void**)&Xh, g_Xh);
    cudaGetSymbolAddress((void**)&W,  g_W);
    cudaGetSymbolAddress((void**)&C,  g_C);

    cudaFuncSetAttribute(gemm_fp16, cudaFuncAttributeMaxDynamicSharedMemorySize, GEMM_SMEM);

    // 1+2 fused: dequant -> W (fp16)  ||  Xh = fp16( FWHT(input*SU)/64 )
    prep_kernel<<<NB_DQ + ROWS_T, 256>>>(input, SU, grid, qidxs, Xh, W);

    // 3. C = fp16( Xh @ W^T )  (fp16 mma.sync, fp32 accumulate)
    dim3 gdim(MDIM / 128, ROWS_T / 128);
    gemm_fp16<<<gdim, 128, GEMM_SMEM>>>(Xh, W, C);

    // 4. out = FWHT(C) * SV / 64
    fwht_sv_kernel<<<ROWS_T, 256>>>(C, out, SV);
}